// round 9
// baseline (speedup 1.0000x reference)
#include <cuda_runtime.h>
#include <cuda_bf16.h>
#include <cstdint>

#define B_   64
#define T_   2048
#define DIN  128
#define H_   512
#define DOUT 128

#define KC   64      // K elems per chunk (128B bf16 rows)
#define TPB  256

#if defined(__CUDA_ARCH__) && (defined(__CUDA_ARCH_FEAT_SM103_ALL) || defined(__CUDA_ARCH_FEAT_SM100_ALL))
#define USE_TC 1
#else
#define USE_TC 0
#endif

// idesc kind::f16: dtype=F32(1<<4) atype=BF16(1<<7) btype=BF16(1<<10) N=128(16<<17) M=128(8<<24)
#define IDESC_128x128 0x8200490u

// SMEM: [0:4) tmem ptr; mbars at 64; chunk buffers at 1024
#define MB_BUFFREE0  64
#define MB_TILERDY0  80
#define MB_SCAND0    96
#define SM_BUF0      1024

// layer (HG=2): W 256rx128B x2 planes (64KB) + X 128rx128B x2 (32KB) = 96KB/chunk
#define L_CHUNK   98304
#define L_SMEM    (1024 + 2*L_CHUNK)      // 197632
// fc (HG=1): W 128r x2 (32KB) + X 128r x2 (32KB) = 64KB/chunk
#define F_CHUNK   65536
#define F_SMEM    (1024 + 2*F_CHUNK)      // 132096

// ---------------- scratch: planar bf16 hi/lo ----------------
__device__ __nv_bfloat16 g_xhi[(size_t)B_ * T_ * DIN];
__device__ __nv_bfloat16 g_xlo[(size_t)B_ * T_ * DIN];
__device__ __nv_bfloat16 g_h1hi[(size_t)B_ * T_ * H_];
__device__ __nv_bfloat16 g_h1lo[(size_t)B_ * T_ * H_];
__device__ __nv_bfloat16 g_h2hi[(size_t)B_ * T_ * H_];
__device__ __nv_bfloat16 g_h2lo[(size_t)B_ * T_ * H_];
__device__ __nv_bfloat16 g_W0hi[H_ * DIN];
__device__ __nv_bfloat16 g_W0lo[H_ * DIN];
__device__ __nv_bfloat16 g_W1hi[H_ * H_];
__device__ __nv_bfloat16 g_W1lo[H_ * H_];
__device__ __nv_bfloat16 g_fWhi[DOUT * H_];
__device__ __nv_bfloat16 g_fWlo[DOUT * H_];

#if USE_TC
// ---------------- PTX helpers ----------------
__device__ __forceinline__ uint32_t smem_to_u32(const void* p) {
    uint32_t a;
    asm("{ .reg .u64 t; cvta.to.shared.u64 t, %1; cvt.u32.u64 %0, t; }" : "=r"(a) : "l"(p));
    return a;
}
__device__ __forceinline__ uint32_t elect_one_pred() {
    uint32_t p;
    asm volatile("{\n\t.reg .pred p;\n\telect.sync _|p, 0xFFFFFFFF;\n\tselp.b32 %0, 1, 0, p;\n\t}" : "=r"(p));
    return p;
}
#define MBAR_INIT(a, c) asm volatile("mbarrier.init.shared.b64 [%0], %1;" :: "r"(a), "r"(c) : "memory")
#define MBAR_INVAL(a)   asm volatile("mbarrier.inval.shared.b64 [%0];" :: "r"(a) : "memory")
#define MBAR_ARRIVE(a)  asm volatile("mbarrier.arrive.shared.b64 _, [%0];" :: "r"(a) : "memory")
#define MBAR_WAIT(a, ph) do {                                                       \
    uint32_t _m = (a), _p = (ph), _d;                                               \
    asm volatile("{\n\t.reg .pred p;\n\t"                                           \
        "mbarrier.try_wait.parity.acquire.cta.shared::cta.b64 p, [%1], %2;\n\t"     \
        "selp.b32 %0, 1, 0, p;\n\t}" : "=r"(_d) : "r"(_m), "r"(_p) : "memory");     \
    if (!_d) {                                                                      \
        asm volatile("{\n\t.reg .pred P1;\n\tWL_%=:\n\t"                            \
            "mbarrier.try_wait.parity.acquire.cta.shared::cta.b64 P1, [%0], %1, 0x989680;\n\t" \
            "@P1 bra.uni WD_%=;\n\tbra.uni WL_%=;\n\tWD_%=:\n\t}"                   \
            :: "r"(_m), "r"(_p) : "memory");                                        \
    }                                                                               \
} while (0)
#define TC_ALLOC(sa, n)   asm volatile("tcgen05.alloc.cta_group::1.sync.aligned.shared::cta.b32 [%0], %1;" :: "r"(sa), "r"(n) : "memory")
#define TC_DEALLOC(t, n)  asm volatile("tcgen05.dealloc.cta_group::1.sync.aligned.b32 %0, %1;" :: "r"(t), "r"(n))
#define TC_RELINQ()       asm volatile("tcgen05.relinquish_alloc_permit.cta_group::1.sync.aligned;")
#define TC_COMMIT(mb)     asm volatile("tcgen05.commit.cta_group::1.mbarrier::arrive::one.shared::cluster.b64 [%0];" :: "r"(mb) : "memory")
#define TC_WAIT_LD()      asm volatile("tcgen05.wait::ld.sync.aligned;" ::: "memory")
#define TC_FENCE_BEFORE() asm volatile("tcgen05.fence::before_thread_sync;" ::: "memory")
#define TC_FENCE_AFTER()  asm volatile("tcgen05.fence::after_thread_sync;" ::: "memory")
#define FENCE_ASYNC()     asm volatile("fence.proxy.async.shared::cta;" ::: "memory")
#define BAR_PROD()        asm volatile("bar.sync 1, 128;" ::: "memory")
#define CP_ASYNC16(d, s)  asm volatile("cp.async.cg.shared.global [%0], [%1], 16;" :: "r"(d), "l"(s) : "memory")
#define CP_COMMIT()       asm volatile("cp.async.commit_group;" ::: "memory")
#define CP_WAIT0()        asm volatile("cp.async.wait_group 0;" ::: "memory")

__device__ __forceinline__ void mma_f16_ss(uint32_t d, uint64_t ad, uint64_t bd, uint32_t en) {
    asm volatile(
        "{\n\t.reg .pred p;\n\tsetp.ne.u32 p, %4, 0;\n\t"
        "tcgen05.mma.cta_group::1.kind::f16 [%0], %1, %2, %3, {%5, %5, %5, %5}, p;\n\t}"
        :: "r"(d), "l"(ad), "l"(bd), "r"(IDESC_128x128), "r"(en), "r"(0u) : "memory");
}
__device__ __forceinline__ uint64_t mk_desc(uint32_t addr) {
    return ((uint64_t)2 << 61) | ((uint64_t)1 << 46) | ((uint64_t)64 << 32)
         | ((uint64_t)1 << 16) | ((uint64_t)(addr >> 4) & 0x3FFF);
}
#define LDTM_X32(r, a)                                                              \
    asm volatile("tcgen05.ld.sync.aligned.32x32b.x32.b32 "                          \
        "{%0,%1,%2,%3,%4,%5,%6,%7,%8,%9,%10,%11,%12,%13,%14,%15,"                   \
        "%16,%17,%18,%19,%20,%21,%22,%23,%24,%25,%26,%27,%28,%29,%30,%31}, [%32];"  \
        : "=r"((r)[0]),"=r"((r)[1]),"=r"((r)[2]),"=r"((r)[3]),                       \
          "=r"((r)[4]),"=r"((r)[5]),"=r"((r)[6]),"=r"((r)[7]),                       \
          "=r"((r)[8]),"=r"((r)[9]),"=r"((r)[10]),"=r"((r)[11]),                     \
          "=r"((r)[12]),"=r"((r)[13]),"=r"((r)[14]),"=r"((r)[15]),                   \
          "=r"((r)[16]),"=r"((r)[17]),"=r"((r)[18]),"=r"((r)[19]),                   \
          "=r"((r)[20]),"=r"((r)[21]),"=r"((r)[22]),"=r"((r)[23]),                   \
          "=r"((r)[24]),"=r"((r)[25]),"=r"((r)[26]),"=r"((r)[27]),                   \
          "=r"((r)[28]),"=r"((r)[29]),"=r"((r)[30]),"=r"((r)[31]) : "r"(a))

// async chunk loader: W = HG*128 rows, X = 128 rows (one batch, 128 timesteps); SW128.
template <int K, int HG>
__device__ __forceinline__ void load_chunk_async(uint32_t smbuf,
        const __nv_bfloat16* __restrict__ Xhi, const __nv_bfloat16* __restrict__ Xlo,
        const __nv_bfloat16* __restrict__ Whi, const __nv_bfloat16* __restrict__ Wlo,
        int h0, int batch, int t0, int kc, int ltid) {
    constexpr uint32_t OWL = HG * 128 * 128;      // W plane bytes
    constexpr uint32_t OXH = 2 * OWL;
    constexpr uint32_t OXL = OXH + 16384;
    // X: row ltid = timestep t0+ltid
    {
        const size_t rowelem = ((size_t)batch * T_ + (t0 + ltid)) * K + kc;
        const char* shi = (const char*)(Xhi + rowelem);
        const char* slo = (const char*)(Xlo + rowelem);
        #pragma unroll
        for (int p = 0; p < 8; p++) {
            uint32_t off = ltid * 128 + p * 16;
            uint32_t sw = off ^ ((off >> 3) & 0x70);
            CP_ASYNC16(smbuf + OXH + sw, shi + p * 16);
            CP_ASYNC16(smbuf + OXL + sw, slo + p * 16);
        }
    }
    // W: rows rr*128 + ltid
    #pragma unroll
    for (int rr = 0; rr < HG; rr++) {
        const int r = rr * 128 + ltid;
        const size_t rowelem = (size_t)(h0 + r) * K + kc;
        const char* shi = (const char*)(Whi + rowelem);
        const char* slo = (const char*)(Wlo + rowelem);
        #pragma unroll
        for (int p = 0; p < 8; p++) {
            uint32_t off = r * 128 + p * 16;
            uint32_t sw = off ^ ((off >> 3) & 0x70);
            CP_ASYNC16(smbuf + sw, shi + p * 16);          // WH at offset 0
            CP_ASYNC16(smbuf + OWL + sw, slo + p * 16);    // WL
        }
    }
    CP_COMMIT();
    CP_WAIT0();
    BAR_PROD();
}

// producer MMA issue for one chunk: HG regions x 3 passes x 4 K-steps, N=128.
template <int HG>
__device__ __forceinline__ void issue_mmas(uint32_t smbuf, uint32_t tmem, int tbuf,
                                           int first_chunk) {
    constexpr uint32_t OWL = HG * 128 * 128;
    constexpr uint32_t OXH = 2 * OWL;
    constexpr uint32_t OXL = OXH + 16384;
    const uint64_t dWH = mk_desc(smbuf), dWL = mk_desc(smbuf + OWL);
    const uint64_t dXH = mk_desc(smbuf + OXH), dXL = mk_desc(smbuf + OXL);
    #pragma unroll
    for (int r = 0; r < HG; r++) {
        const uint32_t dacc = tmem + tbuf * (HG * 128) + r * 128;
        const uint64_t wofs = (uint64_t)r * 1024;   // 128 rows * 128B / 16
        #pragma unroll
        for (int k = 0; k < 4; k++) {
            const uint64_t o = (uint64_t)(k * 2);
            mma_f16_ss(dacc, dWH + wofs + o, dXH + o, (first_chunk && k == 0) ? 0u : 1u);
            mma_f16_ss(dacc, dWH + wofs + o, dXL + o, 1u);
            mma_f16_ss(dacc, dWL + wofs + o, dXH + o, 1u);
        }
    }
}
#endif  // USE_TC

// ---------------- fp32 -> planar bf16 hi/lo split ----------------
__global__ void split_kernel(const float* __restrict__ src,
                             __nv_bfloat16* __restrict__ hi,
                             __nv_bfloat16* __restrict__ lo, int n) {
    for (int i = blockIdx.x * blockDim.x + threadIdx.x; i < n; i += gridDim.x * blockDim.x) {
        float v = src[i];
        __nv_bfloat16 h = __float2bfloat16(v);
        hi[i] = h;
        lo[i] = __float2bfloat16(v - __bfloat162float(h));
    }
}

// ================ fused layer: GEMM (bf16x2) + in-register scan ================
// grid (B_, H_/256), block 256. CTA: one batch, 256 channels (2 TMEM regions), 16 t-tiles.
// warps 0-3: scan consumer (thread scans 2 channels); warps 4-7: producer + MMA issue.
template <int K>
__global__ void __launch_bounds__(TPB, 1)
layer_tc(const __nv_bfloat16* __restrict__ Xhi, const __nv_bfloat16* __restrict__ Xlo,
         const __nv_bfloat16* __restrict__ Whi, const __nv_bfloat16* __restrict__ Wlo,
         const float* __restrict__ bl, const float* __restrict__ u, const float* __restrict__ bb,
         __nv_bfloat16* __restrict__ Hhi, __nv_bfloat16* __restrict__ Hlo) {
    extern __shared__ char smem[];
    const int tid = threadIdx.x;
    const int batch = blockIdx.x;
    const int h0 = blockIdx.y * 256;
#if USE_TC
    constexpr int C = K / KC;
    constexpr int NTILES = T_ / 128;
    const uint32_t smb = smem_to_u32(smem);
    const int wid = tid >> 5;

    if (tid == 0) {
        MBAR_INIT(smb + MB_BUFFREE0, 1); MBAR_INIT(smb + MB_BUFFREE0 + 8, 1);
        MBAR_INIT(smb + MB_TILERDY0, 1); MBAR_INIT(smb + MB_TILERDY0 + 8, 1);
        MBAR_INIT(smb + MB_SCAND0, 128); MBAR_INIT(smb + MB_SCAND0 + 8, 128);
    }
    if (wid == 0) { TC_ALLOC(smb, 512); TC_RELINQ(); }
    __syncthreads();
    uint32_t tmem;
    asm volatile("ld.shared.b32 %0, [%1];" : "=r"(tmem) : "r"(smb));

    if (wid >= 4) {
        // ---------------- producer ----------------
        const int ltid = tid - 128;
        int cnt[2] = {0, 0};
        for (int j = 0; j < NTILES; j++) {
            const int t0 = j * 128;
            for (int c = 0; c < C; c++) {
                const int b = (j * C + c) & 1;
                if (cnt[b]) MBAR_WAIT(smb + MB_BUFFREE0 + 8 * b, (cnt[b] - 1) & 1);
                const uint32_t smbuf = smb + SM_BUF0 + b * L_CHUNK;
                load_chunk_async<K, 2>(smbuf, Xhi, Xlo, Whi, Wlo, h0, batch, t0, c * KC, ltid);
                FENCE_ASYNC();
                if (wid == 4 && elect_one_pred()) {
                    if (c == 0 && j >= 2)
                        MBAR_WAIT(smb + MB_SCAND0 + 8 * (j & 1), ((j >> 1) - 1) & 1);
                    issue_mmas<2>(smbuf, tmem, j & 1, c == 0);
                    TC_COMMIT(smb + MB_BUFFREE0 + 8 * b);
                    if (c == C - 1) TC_COMMIT(smb + MB_TILERDY0 + 8 * (j & 1));
                }
                cnt[b]++;
            }
        }
    } else {
        // ---------------- consumer: scan 2 channels per thread (ILP-2) ----------------
        float c0 = 0.0f, c1 = 0.0f;
        const float u0v = u[h0 + tid],       b0v = bl[h0 + tid] + bb[h0 + tid];
        const float u1v = u[h0 + 128 + tid], b1v = bl[h0 + 128 + tid] + bb[h0 + 128 + tid];
        for (int j = 0; j < NTILES; j++) {
            const int t0 = j * 128;
            MBAR_WAIT(smb + MB_TILERDY0 + 8 * (j & 1), (j >> 1) & 1);
            TC_FENCE_AFTER();
            const uint32_t dbase = tmem + (j & 1) * 256;
            #pragma unroll
            for (int cb = 0; cb < 4; cb++) {
                uint32_t d0[32], d1[32];
                LDTM_X32(d0, dbase + cb * 32);          // region 0
                LDTM_X32(d1, dbase + 128 + cb * 32);    // region 1
                TC_WAIT_LD();
                const size_t base = ((size_t)batch * T_ + t0 + cb * 32) * H_ + h0 + tid;
                #pragma unroll
                for (int i = 0; i < 32; i++) {
                    const size_t o0 = base + (size_t)i * H_;
                    float p0 = __uint_as_float(d0[i]) + b0v;
                    float p1 = __uint_as_float(d1[i]) + b1v;
                    c0 = fmaxf(fmaf(u0v, c0, p0), 0.0f);
                    c1 = fmaxf(fmaf(u1v, c1, p1), 0.0f);
                    __nv_bfloat16 h0b = __float2bfloat16(c0);
                    __nv_bfloat16 h1b = __float2bfloat16(c1);
                    Hhi[o0]       = h0b;
                    Hlo[o0]       = __float2bfloat16(c0 - __bfloat162float(h0b));
                    Hhi[o0 + 128] = h1b;
                    Hlo[o0 + 128] = __float2bfloat16(c1 - __bfloat162float(h1b));
                }
            }
            TC_FENCE_BEFORE();
            MBAR_ARRIVE(smb + MB_SCAND0 + 8 * (j & 1));
        }
    }
    __syncthreads();
    if (tid == 0) {
        MBAR_INVAL(smb + MB_BUFFREE0); MBAR_INVAL(smb + MB_BUFFREE0 + 8);
        MBAR_INVAL(smb + MB_TILERDY0); MBAR_INVAL(smb + MB_TILERDY0 + 8);
        MBAR_INVAL(smb + MB_SCAND0);   MBAR_INVAL(smb + MB_SCAND0 + 8);
    }
    __syncthreads();
    if (wid == 0) TC_DEALLOC(tmem, 512);
#else
    // SIMT fallback: thread owns channel h0+tid (256 channels, 256 threads)
    float* xrow = (float*)smem;
    const int h = h0 + tid;
    const float uu = u[h], bi = bl[h] + bb[h];
    const __nv_bfloat16* wh = Whi + (size_t)h * K;
    const __nv_bfloat16* wl = Wlo + (size_t)h * K;
    float hcar = 0.0f;
    for (int t = 0; t < T_; t++) {
        __syncthreads();
        size_t xr = ((size_t)batch * T_ + t) * K;
        for (int i = tid; i < K; i += TPB)
            xrow[i] = __bfloat162float(Xhi[xr + i]) + __bfloat162float(Xlo[xr + i]);
        __syncthreads();
        float acc = 0.0f;
        for (int k = 0; k < K; k++)
            acc += (__bfloat162float(wh[k]) + __bfloat162float(wl[k])) * xrow[k];
        hcar = fmaxf(acc + bi + uu * hcar, 0.0f);
        size_t oi = ((size_t)batch * T_ + t) * H_ + h;
        __nv_bfloat16 hh = __float2bfloat16(hcar);
        Hhi[oi] = hh;
        Hlo[oi] = __float2bfloat16(hcar - __bfloat162float(hh));
    }
#endif
}

// ================ FC: out[b,t,o] = h2 . fcW[o,:] + fcb[o] ================
// grid (B_, 2 tgroups), block 256. 1 region (128 out channels), 8 t-tiles, K=512.
__global__ void __launch_bounds__(TPB, 1)
fc_tc(const __nv_bfloat16* __restrict__ Xhi, const __nv_bfloat16* __restrict__ Xlo,
      const __nv_bfloat16* __restrict__ Whi, const __nv_bfloat16* __restrict__ Wlo,
      const float* __restrict__ bias, float* __restrict__ out) {
    extern __shared__ char smem[];
    const int tid = threadIdx.x;
    const int batch = blockIdx.x;
    const int tg = blockIdx.y;
#if USE_TC
    constexpr int C = H_ / KC;    // 8
    constexpr int NTILES = 8;
    const uint32_t smb = smem_to_u32(smem);
    const int wid = tid >> 5;

    if (tid == 0) {
        MBAR_INIT(smb + MB_BUFFREE0, 1); MBAR_INIT(smb + MB_BUFFREE0 + 8, 1);
        MBAR_INIT(smb + MB_TILERDY0, 1); MBAR_INIT(smb + MB_TILERDY0 + 8, 1);
        MBAR_INIT(smb + MB_SCAND0, 128); MBAR_INIT(smb + MB_SCAND0 + 8, 128);
    }
    if (wid == 0) { TC_ALLOC(smb, 256); TC_RELINQ(); }
    __syncthreads();
    uint32_t tmem;
    asm volatile("ld.shared.b32 %0, [%1];" : "=r"(tmem) : "r"(smb));

    if (wid >= 4) {
        const int ltid = tid - 128;
        int cnt[2] = {0, 0};
        for (int j = 0; j < NTILES; j++) {
            const int t0 = tg * 1024 + j * 128;
            for (int c = 0; c < C; c++) {
                const int b = (j * C + c) & 1;
                if (cnt[b]) MBAR_WAIT(smb + MB_BUFFREE0 + 8 * b, (cnt[b] - 1) & 1);
                const uint32_t smbuf = smb + SM_BUF0 + b * F_CHUNK;
                load_chunk_async<H_, 1>(smbuf, Xhi, Xlo, Whi, Wlo, 0, batch, t0, c * KC, ltid);
                FENCE_ASYNC();
                if (wid == 4 && elect_one_pred()) {
                    if (c == 0 && j >= 2)
                        MBAR_WAIT(smb + MB_SCAND0 + 8 * (j & 1), ((j >> 1) - 1) & 1);
                    issue_mmas<1>(smbuf, tmem, j & 1, c == 0);
                    TC_COMMIT(smb + MB_BUFFREE0 + 8 * b);
                    if (c == C - 1) TC_COMMIT(smb + MB_TILERDY0 + 8 * (j & 1));
                }
                cnt[b]++;
            }
        }
    } else {
        const float bo = bias[tid];
        for (int j = 0; j < NTILES; j++) {
            const int t0 = tg * 1024 + j * 128;
            MBAR_WAIT(smb + MB_TILERDY0 + 8 * (j & 1), (j >> 1) & 1);
            TC_FENCE_AFTER();
            const uint32_t dbase = tmem + (j & 1) * 128;
            #pragma unroll
            for (int cb = 0; cb < 4; cb++) {
                uint32_t d[32];
                LDTM_X32(d, dbase + cb * 32);
                TC_WAIT_LD();
                float* op = out + ((size_t)batch * T_ + t0 + cb * 32) * DOUT + tid;
                #pragma unroll
                for (int i = 0; i < 32; i++)
                    op[(size_t)i * DOUT] = __uint_as_float(d[i]) + bo;
            }
            TC_FENCE_BEFORE();
            MBAR_ARRIVE(smb + MB_SCAND0 + 8 * (j & 1));
        }
    }
    __syncthreads();
    if (tid == 0) {
        MBAR_INVAL(smb + MB_BUFFREE0); MBAR_INVAL(smb + MB_BUFFREE0 + 8);
        MBAR_INVAL(smb + MB_TILERDY0); MBAR_INVAL(smb + MB_TILERDY0 + 8);
        MBAR_INVAL(smb + MB_SCAND0);   MBAR_INVAL(smb + MB_SCAND0 + 8);
    }
    __syncthreads();
    if (wid == 0) TC_DEALLOC(tmem, 256);
#else
    // SIMT fallback
    float* xrow = (float*)smem;
    const __nv_bfloat16* wh = Whi + (size_t)(tid < 128 ? tid : 0) * H_;
    const __nv_bfloat16* wl = Wlo + (size_t)(tid < 128 ? tid : 0) * H_;
    float bo = (tid < 128) ? bias[tid] : 0.0f;
    for (int tt = 0; tt < 1024; tt++) {
        const int t = tg * 1024 + tt;
        __syncthreads();
        size_t xr = ((size_t)batch * T_ + t) * H_;
        for (int i = tid; i < H_; i += TPB)
            xrow[i] = __bfloat162float(Xhi[xr + i]) + __bfloat162float(Xlo[xr + i]);
        __syncthreads();
        if (tid < 128) {
            float acc = 0.0f;
            for (int k = 0; k < H_; k++)
                acc += (__bfloat162float(wh[k]) + __bfloat162float(wl[k])) * xrow[k];
            out[((size_t)batch * T_ + t) * DOUT + tid] = acc + bo;
        }
    }
#endif
}

extern "C" void kernel_launch(void* const* d_in, const int* in_sizes, int n_in,
                              void* d_out, int out_size) {
    const float* x   = (const float*)d_in[0];
    const float* W0  = (const float*)d_in[1];
    const float* bl0 = (const float*)d_in[2];
    const float* u0  = (const float*)d_in[3];
    const float* bb0 = (const float*)d_in[4];
    const float* W1  = (const float*)d_in[5];
    const float* bl1 = (const float*)d_in[6];
    const float* u1  = (const float*)d_in[7];
    const float* bb1 = (const float*)d_in[8];
    const float* fcW = (const float*)d_in[9];
    const float* fcb = (const float*)d_in[10];
    float* out = (float*)d_out;

    __nv_bfloat16 *xhi, *xlo, *h1hi, *h1lo, *h2hi, *h2lo;
    __nv_bfloat16 *w0hi, *w0lo, *w1hi, *w1lo, *fwhi, *fwlo;
    cudaGetSymbolAddress((void**)&xhi,  g_xhi);
    cudaGetSymbolAddress((void**)&xlo,  g_xlo);
    cudaGetSymbolAddress((void**)&h1hi, g_h1hi);
    cudaGetSymbolAddress((void**)&h1lo, g_h1lo);
    cudaGetSymbolAddress((void**)&h2hi, g_h2hi);
    cudaGetSymbolAddress((void**)&h2lo, g_h2lo);
    cudaGetSymbolAddress((void**)&w0hi, g_W0hi);
    cudaGetSymbolAddress((void**)&w0lo, g_W0lo);
    cudaGetSymbolAddress((void**)&w1hi, g_W1hi);
    cudaGetSymbolAddress((void**)&w1lo, g_W1lo);
    cudaGetSymbolAddress((void**)&fwhi, g_fWhi);
    cudaGetSymbolAddress((void**)&fwlo, g_fWlo);

    cudaFuncSetAttribute(layer_tc<DIN>, cudaFuncAttributeMaxDynamicSharedMemorySize, L_SMEM);
    cudaFuncSetAttribute(layer_tc<H_>,  cudaFuncAttributeMaxDynamicSharedMemorySize, L_SMEM);
    cudaFuncSetAttribute(fc_tc,         cudaFuncAttributeMaxDynamicSharedMemorySize, F_SMEM);

    split_kernel<<<1024, 256>>>(x,   xhi,  xlo,  B_ * T_ * DIN);
    split_kernel<<<64,   256>>>(W0,  w0hi, w0lo, H_ * DIN);
    split_kernel<<<256,  256>>>(W1,  w1hi, w1lo, H_ * H_);
    split_kernel<<<64,   256>>>(fcW, fwhi, fwlo, DOUT * H_);

    dim3 lgrid(B_, H_ / 256);         // (64, 2)
    layer_tc<DIN><<<lgrid, TPB, L_SMEM>>>(xhi, xlo, w0hi, w0lo, bl0, u0, bb0, h1hi, h1lo);
    layer_tc<H_> <<<lgrid, TPB, L_SMEM>>>(h1hi, h1lo, w1hi, w1lo, bl1, u1, bb1, h2hi, h2lo);
    dim3 fgrid(B_, 2);                // (64, 2)
    fc_tc<<<fgrid, TPB, F_SMEM>>>(h2hi, h2lo, fwhi, fwlo, fcb, out);
}

// round 10
// speedup vs baseline: 1.0231x; 1.0231x over previous
#include <cuda_runtime.h>
#include <cuda_bf16.h>
#include <cstdint>

#define B_   64
#define T_   2048
#define DIN  128
#define H_   512
#define DOUT 128

#define KC   64      // K elems per chunk (128B bf16 rows)
#define TPB  288     // 4 scan warps | 4 loader warps | 1 MMA warp

#if defined(__CUDA_ARCH__) && (defined(__CUDA_ARCH_FEAT_SM103_ALL) || defined(__CUDA_ARCH_FEAT_SM100_ALL))
#define USE_TC 1
#else
#define USE_TC 0
#endif

// idesc kind::f16: dtype=F32(1<<4) atype=BF16(1<<7) btype=BF16(1<<10) N=128(16<<17) M=128(8<<24)
#define IDESC_128x128 0x8200490u

// SMEM: [0:4) tmem ptr; mbars at 64; chunk buffers at 1024
#define MB_BUFFREE0  64      // +8*b
#define MB_TILERDY0  80      // +8*(j&1)
#define MB_SCAND0    96      // +8*(j&1)
#define MB_LOADED0   112     // +8*b
#define SM_BUF0      1024

// layer (HG=2): W 256rx128B x2 planes (64KB) + X 128rx128B x2 (32KB) = 96KB/chunk
#define L_CHUNK   98304
#define L_SMEM    (1024 + 2*L_CHUNK)
// fc (HG=1): 64KB/chunk
#define F_CHUNK   65536
#define F_SMEM    (1024 + 2*F_CHUNK)

// ---------------- scratch: planar bf16 hi/lo ----------------
__device__ __nv_bfloat16 g_xhi[(size_t)B_ * T_ * DIN];
__device__ __nv_bfloat16 g_xlo[(size_t)B_ * T_ * DIN];
__device__ __nv_bfloat16 g_h1hi[(size_t)B_ * T_ * H_];
__device__ __nv_bfloat16 g_h1lo[(size_t)B_ * T_ * H_];
__device__ __nv_bfloat16 g_h2hi[(size_t)B_ * T_ * H_];
__device__ __nv_bfloat16 g_h2lo[(size_t)B_ * T_ * H_];
__device__ __nv_bfloat16 g_W0hi[H_ * DIN];
__device__ __nv_bfloat16 g_W0lo[H_ * DIN];
__device__ __nv_bfloat16 g_W1hi[H_ * H_];
__device__ __nv_bfloat16 g_W1lo[H_ * H_];
__device__ __nv_bfloat16 g_fWhi[DOUT * H_];
__device__ __nv_bfloat16 g_fWlo[DOUT * H_];

#if USE_TC
// ---------------- PTX helpers ----------------
__device__ __forceinline__ uint32_t smem_to_u32(const void* p) {
    uint32_t a;
    asm("{ .reg .u64 t; cvta.to.shared.u64 t, %1; cvt.u32.u64 %0, t; }" : "=r"(a) : "l"(p));
    return a;
}
__device__ __forceinline__ uint32_t elect_one_pred() {
    uint32_t p;
    asm volatile("{\n\t.reg .pred p;\n\telect.sync _|p, 0xFFFFFFFF;\n\tselp.b32 %0, 1, 0, p;\n\t}" : "=r"(p));
    return p;
}
#define MBAR_INIT(a, c) asm volatile("mbarrier.init.shared.b64 [%0], %1;" :: "r"(a), "r"(c) : "memory")
#define MBAR_INVAL(a)   asm volatile("mbarrier.inval.shared.b64 [%0];" :: "r"(a) : "memory")
#define MBAR_ARRIVE(a)  asm volatile("mbarrier.arrive.shared.b64 _, [%0];" :: "r"(a) : "memory")
#define MBAR_WAIT(a, ph) do {                                                       \
    uint32_t _m = (a), _p = (ph), _d;                                               \
    asm volatile("{\n\t.reg .pred p;\n\t"                                           \
        "mbarrier.try_wait.parity.acquire.cta.shared::cta.b64 p, [%1], %2;\n\t"     \
        "selp.b32 %0, 1, 0, p;\n\t}" : "=r"(_d) : "r"(_m), "r"(_p) : "memory");     \
    if (!_d) {                                                                      \
        asm volatile("{\n\t.reg .pred P1;\n\tWL_%=:\n\t"                            \
            "mbarrier.try_wait.parity.acquire.cta.shared::cta.b64 P1, [%0], %1, 0x989680;\n\t" \
            "@P1 bra.uni WD_%=;\n\tbra.uni WL_%=;\n\tWD_%=:\n\t}"                   \
            :: "r"(_m), "r"(_p) : "memory");                                        \
    }                                                                               \
} while (0)
#define TC_ALLOC(sa, n)   asm volatile("tcgen05.alloc.cta_group::1.sync.aligned.shared::cta.b32 [%0], %1;" :: "r"(sa), "r"(n) : "memory")
#define TC_DEALLOC(t, n)  asm volatile("tcgen05.dealloc.cta_group::1.sync.aligned.b32 %0, %1;" :: "r"(t), "r"(n))
#define TC_RELINQ()       asm volatile("tcgen05.relinquish_alloc_permit.cta_group::1.sync.aligned;")
#define TC_COMMIT(mb)     asm volatile("tcgen05.commit.cta_group::1.mbarrier::arrive::one.shared::cluster.b64 [%0];" :: "r"(mb) : "memory")
#define TC_WAIT_LD()      asm volatile("tcgen05.wait::ld.sync.aligned;" ::: "memory")
#define TC_FENCE_BEFORE() asm volatile("tcgen05.fence::before_thread_sync;" ::: "memory")
#define TC_FENCE_AFTER()  asm volatile("tcgen05.fence::after_thread_sync;" ::: "memory")
#define FENCE_ASYNC()     asm volatile("fence.proxy.async.shared::cta;" ::: "memory")
#define BAR_LOAD()        asm volatile("bar.sync 1, 128;" ::: "memory")
#define CP_ASYNC16(d, s)  asm volatile("cp.async.cg.shared.global [%0], [%1], 16;" :: "r"(d), "l"(s) : "memory")
#define CP_COMMIT()       asm volatile("cp.async.commit_group;" ::: "memory")
#define CP_WAIT0()        asm volatile("cp.async.wait_group 0;" ::: "memory")

__device__ __forceinline__ void mma_f16_ss(uint32_t d, uint64_t ad, uint64_t bd, uint32_t en) {
    asm volatile(
        "{\n\t.reg .pred p;\n\tsetp.ne.u32 p, %4, 0;\n\t"
        "tcgen05.mma.cta_group::1.kind::f16 [%0], %1, %2, %3, {%5, %5, %5, %5}, p;\n\t}"
        :: "r"(d), "l"(ad), "l"(bd), "r"(IDESC_128x128), "r"(en), "r"(0u) : "memory");
}
__device__ __forceinline__ uint64_t mk_desc(uint32_t addr) {
    return ((uint64_t)2 << 61) | ((uint64_t)1 << 46) | ((uint64_t)64 << 32)
         | ((uint64_t)1 << 16) | ((uint64_t)(addr >> 4) & 0x3FFF);
}
#define LDTM_X32(r, a)                                                              \
    asm volatile("tcgen05.ld.sync.aligned.32x32b.x32.b32 "                          \
        "{%0,%1,%2,%3,%4,%5,%6,%7,%8,%9,%10,%11,%12,%13,%14,%15,"                   \
        "%16,%17,%18,%19,%20,%21,%22,%23,%24,%25,%26,%27,%28,%29,%30,%31}, [%32];"  \
        : "=r"((r)[0]),"=r"((r)[1]),"=r"((r)[2]),"=r"((r)[3]),                       \
          "=r"((r)[4]),"=r"((r)[5]),"=r"((r)[6]),"=r"((r)[7]),                       \
          "=r"((r)[8]),"=r"((r)[9]),"=r"((r)[10]),"=r"((r)[11]),                     \
          "=r"((r)[12]),"=r"((r)[13]),"=r"((r)[14]),"=r"((r)[15]),                   \
          "=r"((r)[16]),"=r"((r)[17]),"=r"((r)[18]),"=r"((r)[19]),                   \
          "=r"((r)[20]),"=r"((r)[21]),"=r"((r)[22]),"=r"((r)[23]),                   \
          "=r"((r)[24]),"=r"((r)[25]),"=r"((r)[26]),"=r"((r)[27]),                   \
          "=r"((r)[28]),"=r"((r)[29]),"=r"((r)[30]),"=r"((r)[31]) : "r"(a))

// async chunk loader: W = HG*128 rows, X = 128 rows (one batch, 128 timesteps); SW128.
template <int K, int HG>
__device__ __forceinline__ void load_chunk_async(uint32_t smbuf,
        const __nv_bfloat16* __restrict__ Xhi, const __nv_bfloat16* __restrict__ Xlo,
        const __nv_bfloat16* __restrict__ Whi, const __nv_bfloat16* __restrict__ Wlo,
        int h0, int batch, int t0, int kc, int ltid) {
    constexpr uint32_t OWL = HG * 128 * 128;
    constexpr uint32_t OXH = 2 * OWL;
    constexpr uint32_t OXL = OXH + 16384;
    {
        const size_t rowelem = ((size_t)batch * T_ + (t0 + ltid)) * K + kc;
        const char* shi = (const char*)(Xhi + rowelem);
        const char* slo = (const char*)(Xlo + rowelem);
        #pragma unroll
        for (int p = 0; p < 8; p++) {
            uint32_t off = ltid * 128 + p * 16;
            uint32_t sw = off ^ ((off >> 3) & 0x70);
            CP_ASYNC16(smbuf + OXH + sw, shi + p * 16);
            CP_ASYNC16(smbuf + OXL + sw, slo + p * 16);
        }
    }
    #pragma unroll
    for (int rr = 0; rr < HG; rr++) {
        const int r = rr * 128 + ltid;
        const size_t rowelem = (size_t)(h0 + r) * K + kc;
        const char* shi = (const char*)(Whi + rowelem);
        const char* slo = (const char*)(Wlo + rowelem);
        #pragma unroll
        for (int p = 0; p < 8; p++) {
            uint32_t off = r * 128 + p * 16;
            uint32_t sw = off ^ ((off >> 3) & 0x70);
            CP_ASYNC16(smbuf + sw, shi + p * 16);
            CP_ASYNC16(smbuf + OWL + sw, slo + p * 16);
        }
    }
    CP_COMMIT();
    CP_WAIT0();
    BAR_LOAD();
}

// MMA issue for one chunk: HG regions x 3 passes x 4 K-steps, N=128.
template <int HG>
__device__ __forceinline__ void issue_mmas(uint32_t smbuf, uint32_t tmem, int tbuf,
                                           int first_chunk) {
    constexpr uint32_t OWL = HG * 128 * 128;
    constexpr uint32_t OXH = 2 * OWL;
    constexpr uint32_t OXL = OXH + 16384;
    const uint64_t dWH = mk_desc(smbuf), dWL = mk_desc(smbuf + OWL);
    const uint64_t dXH = mk_desc(smbuf + OXH), dXL = mk_desc(smbuf + OXL);
    #pragma unroll
    for (int r = 0; r < HG; r++) {
        const uint32_t dacc = tmem + tbuf * (HG * 128) + r * 128;
        const uint64_t wofs = (uint64_t)r * 1024;
        #pragma unroll
        for (int k = 0; k < 4; k++) {
            const uint64_t o = (uint64_t)(k * 2);
            mma_f16_ss(dacc, dWH + wofs + o, dXH + o, (first_chunk && k == 0) ? 0u : 1u);
            mma_f16_ss(dacc, dWH + wofs + o, dXL + o, 1u);
            mma_f16_ss(dacc, dWL + wofs + o, dXH + o, 1u);
        }
    }
}
#endif  // USE_TC

// ---------------- fp32 -> planar bf16 hi/lo split ----------------
__global__ void split_kernel(const float* __restrict__ src,
                             __nv_bfloat16* __restrict__ hi,
                             __nv_bfloat16* __restrict__ lo, int n) {
    for (int i = blockIdx.x * blockDim.x + threadIdx.x; i < n; i += gridDim.x * blockDim.x) {
        float v = src[i];
        __nv_bfloat16 h = __float2bfloat16(v);
        hi[i] = h;
        lo[i] = __float2bfloat16(v - __bfloat162float(h));
    }
}

#if USE_TC
// shared kernel body skeleton pieces are inlined per kernel below.
#endif

// ================ fused layer: GEMM (bf16x2) + in-register scan ================
// grid (B_, H_/256), block 288. warps 0-3 scan | 4-7 load | 8 MMA issue.
template <int K>
__global__ void __launch_bounds__(TPB, 1)
layer_tc(const __nv_bfloat16* __restrict__ Xhi, const __nv_bfloat16* __restrict__ Xlo,
         const __nv_bfloat16* __restrict__ Whi, const __nv_bfloat16* __restrict__ Wlo,
         const float* __restrict__ bl, const float* __restrict__ u, const float* __restrict__ bb,
         __nv_bfloat16* __restrict__ Hhi, __nv_bfloat16* __restrict__ Hlo) {
    extern __shared__ char smem[];
    const int tid = threadIdx.x;
    const int batch = blockIdx.x;
    const int h0 = blockIdx.y * 256;
#if USE_TC
    constexpr int C = K / KC;
    constexpr int NTILES = T_ / 128;
    const uint32_t smb = smem_to_u32(smem);
    const int wid = tid >> 5;

    if (tid == 0) {
        MBAR_INIT(smb + MB_BUFFREE0, 1); MBAR_INIT(smb + MB_BUFFREE0 + 8, 1);
        MBAR_INIT(smb + MB_TILERDY0, 1); MBAR_INIT(smb + MB_TILERDY0 + 8, 1);
        MBAR_INIT(smb + MB_SCAND0, 128); MBAR_INIT(smb + MB_SCAND0 + 8, 128);
        MBAR_INIT(smb + MB_LOADED0, 1);  MBAR_INIT(smb + MB_LOADED0 + 8, 1);
    }
    if (wid == 0) { TC_ALLOC(smb, 512); TC_RELINQ(); }
    __syncthreads();
    uint32_t tmem;
    asm volatile("ld.shared.b32 %0, [%1];" : "=r"(tmem) : "r"(smb));

    if (wid >= 4 && wid < 8) {
        // ---------------- loaders only ----------------
        const int ltid = tid - 128;
        int cnt[2] = {0, 0};
        for (int j = 0; j < NTILES; j++) {
            const int t0 = j * 128;
            for (int c = 0; c < C; c++) {
                const int b = (j * C + c) & 1;
                if (cnt[b]) MBAR_WAIT(smb + MB_BUFFREE0 + 8 * b, (cnt[b] - 1) & 1);
                const uint32_t smbuf = smb + SM_BUF0 + b * L_CHUNK;
                load_chunk_async<K, 2>(smbuf, Xhi, Xlo, Whi, Wlo, h0, batch, t0, c * KC, ltid);
                if (ltid == 0) MBAR_ARRIVE(smb + MB_LOADED0 + 8 * b);
                cnt[b]++;
            }
        }
    } else if (wid == 8) {
        // ---------------- MMA issue only ----------------
        int mcnt[2] = {0, 0};
        for (int j = 0; j < NTILES; j++) {
            for (int c = 0; c < C; c++) {
                const int b = (j * C + c) & 1;
                MBAR_WAIT(smb + MB_LOADED0 + 8 * b, mcnt[b] & 1);
                mcnt[b]++;
                if (c == 0 && j >= 2)
                    MBAR_WAIT(smb + MB_SCAND0 + 8 * (j & 1), ((j >> 1) - 1) & 1);
                FENCE_ASYNC();
                if (elect_one_pred()) {
                    const uint32_t smbuf = smb + SM_BUF0 + b * L_CHUNK;
                    issue_mmas<2>(smbuf, tmem, j & 1, c == 0);
                    TC_COMMIT(smb + MB_BUFFREE0 + 8 * b);
                    if (c == C - 1) TC_COMMIT(smb + MB_TILERDY0 + 8 * (j & 1));
                }
            }
        }
    } else {
        // ---------------- consumer: scan 2 channels per thread ----------------
        float c0 = 0.0f, c1 = 0.0f;
        const float u0v = u[h0 + tid],       b0v = bl[h0 + tid] + bb[h0 + tid];
        const float u1v = u[h0 + 128 + tid], b1v = bl[h0 + 128 + tid] + bb[h0 + 128 + tid];
        for (int j = 0; j < NTILES; j++) {
            const int t0 = j * 128;
            MBAR_WAIT(smb + MB_TILERDY0 + 8 * (j & 1), (j >> 1) & 1);
            TC_FENCE_AFTER();
            const uint32_t dbase = tmem + (j & 1) * 256;
            #pragma unroll
            for (int cb = 0; cb < 4; cb++) {
                uint32_t d0[32], d1[32];
                LDTM_X32(d0, dbase + cb * 32);
                LDTM_X32(d1, dbase + 128 + cb * 32);
                TC_WAIT_LD();
                const size_t base = ((size_t)batch * T_ + t0 + cb * 32) * H_ + h0 + tid;
                #pragma unroll
                for (int i = 0; i < 32; i++) {
                    const size_t o0 = base + (size_t)i * H_;
                    float p0 = __uint_as_float(d0[i]) + b0v;
                    float p1 = __uint_as_float(d1[i]) + b1v;
                    c0 = fmaxf(fmaf(u0v, c0, p0), 0.0f);
                    c1 = fmaxf(fmaf(u1v, c1, p1), 0.0f);
                    __nv_bfloat16 h0b = __float2bfloat16(c0);
                    __nv_bfloat16 h1b = __float2bfloat16(c1);
                    Hhi[o0]       = h0b;
                    Hlo[o0]       = __float2bfloat16(c0 - __bfloat162float(h0b));
                    Hhi[o0 + 128] = h1b;
                    Hlo[o0 + 128] = __float2bfloat16(c1 - __bfloat162float(h1b));
                }
            }
            TC_FENCE_BEFORE();
            MBAR_ARRIVE(smb + MB_SCAND0 + 8 * (j & 1));
        }
    }
    __syncthreads();
    if (tid == 0) {
        MBAR_INVAL(smb + MB_BUFFREE0); MBAR_INVAL(smb + MB_BUFFREE0 + 8);
        MBAR_INVAL(smb + MB_TILERDY0); MBAR_INVAL(smb + MB_TILERDY0 + 8);
        MBAR_INVAL(smb + MB_SCAND0);   MBAR_INVAL(smb + MB_SCAND0 + 8);
        MBAR_INVAL(smb + MB_LOADED0);  MBAR_INVAL(smb + MB_LOADED0 + 8);
    }
    __syncthreads();
    if (wid == 0) TC_DEALLOC(tmem, 512);
#else
    // SIMT fallback: thread tid<256 owns channel h0+tid
    float* xrow = (float*)smem;
    const int hh = h0 + (tid < 256 ? tid : 0);
    const float uu = u[hh], bi = bl[hh] + bb[hh];
    const __nv_bfloat16* wh = Whi + (size_t)hh * K;
    const __nv_bfloat16* wl = Wlo + (size_t)hh * K;
    float hcar = 0.0f;
    for (int t = 0; t < T_; t++) {
        __syncthreads();
        size_t xr = ((size_t)batch * T_ + t) * K;
        for (int i = tid; i < K; i += blockDim.x)
            xrow[i] = __bfloat162float(Xhi[xr + i]) + __bfloat162float(Xlo[xr + i]);
        __syncthreads();
        if (tid < 256) {
            float acc = 0.0f;
            for (int k = 0; k < K; k++)
                acc += (__bfloat162float(wh[k]) + __bfloat162float(wl[k])) * xrow[k];
            hcar = fmaxf(acc + bi + uu * hcar, 0.0f);
            size_t oi = ((size_t)batch * T_ + t) * H_ + hh;
            __nv_bfloat16 hb = __float2bfloat16(hcar);
            Hhi[oi] = hb;
            Hlo[oi] = __float2bfloat16(hcar - __bfloat162float(hb));
        }
    }
#endif
}

// ================ FC ================
// grid (B_, 2), block 288. 1 region, 8 t-tiles, K=512.
__global__ void __launch_bounds__(TPB, 1)
fc_tc(const __nv_bfloat16* __restrict__ Xhi, const __nv_bfloat16* __restrict__ Xlo,
      const __nv_bfloat16* __restrict__ Whi, const __nv_bfloat16* __restrict__ Wlo,
      const float* __restrict__ bias, float* __restrict__ out) {
    extern __shared__ char smem[];
    const int tid = threadIdx.x;
    const int batch = blockIdx.x;
    const int tg = blockIdx.y;
#if USE_TC
    constexpr int C = H_ / KC;    // 8
    constexpr int NTILES = 8;
    const uint32_t smb = smem_to_u32(smem);
    const int wid = tid >> 5;

    if (tid == 0) {
        MBAR_INIT(smb + MB_BUFFREE0, 1); MBAR_INIT(smb + MB_BUFFREE0 + 8, 1);
        MBAR_INIT(smb + MB_TILERDY0, 1); MBAR_INIT(smb + MB_TILERDY0 + 8, 1);
        MBAR_INIT(smb + MB_SCAND0, 128); MBAR_INIT(smb + MB_SCAND0 + 8, 128);
        MBAR_INIT(smb + MB_LOADED0, 1);  MBAR_INIT(smb + MB_LOADED0 + 8, 1);
    }
    if (wid == 0) { TC_ALLOC(smb, 256); TC_RELINQ(); }
    __syncthreads();
    uint32_t tmem;
    asm volatile("ld.shared.b32 %0, [%1];" : "=r"(tmem) : "r"(smb));

    if (wid >= 4 && wid < 8) {
        const int ltid = tid - 128;
        int cnt[2] = {0, 0};
        for (int j = 0; j < NTILES; j++) {
            const int t0 = tg * 1024 + j * 128;
            for (int c = 0; c < C; c++) {
                const int b = (j * C + c) & 1;
                if (cnt[b]) MBAR_WAIT(smb + MB_BUFFREE0 + 8 * b, (cnt[b] - 1) & 1);
                const uint32_t smbuf = smb + SM_BUF0 + b * F_CHUNK;
                load_chunk_async<H_, 1>(smbuf, Xhi, Xlo, Whi, Wlo, 0, batch, t0, c * KC, ltid);
                if (ltid == 0) MBAR_ARRIVE(smb + MB_LOADED0 + 8 * b);
                cnt[b]++;
            }
        }
    } else if (wid == 8) {
        int mcnt[2] = {0, 0};
        for (int j = 0; j < NTILES; j++) {
            for (int c = 0; c < C; c++) {
                const int b = (j * C + c) & 1;
                MBAR_WAIT(smb + MB_LOADED0 + 8 * b, mcnt[b] & 1);
                mcnt[b]++;
                if (c == 0 && j >= 2)
                    MBAR_WAIT(smb + MB_SCAND0 + 8 * (j & 1), ((j >> 1) - 1) & 1);
                FENCE_ASYNC();
                if (elect_one_pred()) {
                    const uint32_t smbuf = smb + SM_BUF0 + b * F_CHUNK;
                    issue_mmas<1>(smbuf, tmem, j & 1, c == 0);
                    TC_COMMIT(smb + MB_BUFFREE0 + 8 * b);
                    if (c == C - 1) TC_COMMIT(smb + MB_TILERDY0 + 8 * (j & 1));
                }
            }
        }
    } else {
        const float bo = bias[tid];
        for (int j = 0; j < NTILES; j++) {
            const int t0 = tg * 1024 + j * 128;
            MBAR_WAIT(smb + MB_TILERDY0 + 8 * (j & 1), (j >> 1) & 1);
            TC_FENCE_AFTER();
            const uint32_t dbase = tmem + (j & 1) * 128;
            #pragma unroll
            for (int cb = 0; cb < 4; cb++) {
                uint32_t d[32];
                LDTM_X32(d, dbase + cb * 32);
                TC_WAIT_LD();
                float* op = out + ((size_t)batch * T_ + t0 + cb * 32) * DOUT + tid;
                #pragma unroll
                for (int i = 0; i < 32; i++)
                    op[(size_t)i * DOUT] = __uint_as_float(d[i]) + bo;
            }
            TC_FENCE_BEFORE();
            MBAR_ARRIVE(smb + MB_SCAND0 + 8 * (j & 1));
        }
    }
    __syncthreads();
    if (tid == 0) {
        MBAR_INVAL(smb + MB_BUFFREE0); MBAR_INVAL(smb + MB_BUFFREE0 + 8);
        MBAR_INVAL(smb + MB_TILERDY0); MBAR_INVAL(smb + MB_TILERDY0 + 8);
        MBAR_INVAL(smb + MB_SCAND0);   MBAR_INVAL(smb + MB_SCAND0 + 8);
        MBAR_INVAL(smb + MB_LOADED0);  MBAR_INVAL(smb + MB_LOADED0 + 8);
    }
    __syncthreads();
    if (wid == 0) TC_DEALLOC(tmem, 256);
#else
    // SIMT fallback
    float* xrow = (float*)smem;
    const __nv_bfloat16* wh = Whi + (size_t)(tid < 128 ? tid : 0) * H_;
    const __nv_bfloat16* wl = Wlo + (size_t)(tid < 128 ? tid : 0) * H_;
    float bo = (tid < 128) ? bias[tid] : 0.0f;
    for (int tt = 0; tt < 1024; tt++) {
        const int t = tg * 1024 + tt;
        __syncthreads();
        size_t xr = ((size_t)batch * T_ + t) * H_;
        for (int i = tid; i < H_; i += blockDim.x)
            xrow[i] = __bfloat162float(Xhi[xr + i]) + __bfloat162float(Xlo[xr + i]);
        __syncthreads();
        if (tid < 128) {
            float acc = 0.0f;
            for (int k = 0; k < H_; k++)
                acc += (__bfloat162float(wh[k]) + __bfloat162float(wl[k])) * xrow[k];
            out[((size_t)batch * T_ + t) * DOUT + tid] = acc + bo;
        }
    }
#endif
}

extern "C" void kernel_launch(void* const* d_in, const int* in_sizes, int n_in,
                              void* d_out, int out_size) {
    const float* x   = (const float*)d_in[0];
    const float* W0  = (const float*)d_in[1];
    const float* bl0 = (const float*)d_in[2];
    const float* u0  = (const float*)d_in[3];
    const float* bb0 = (const float*)d_in[4];
    const float* W1  = (const float*)d_in[5];
    const float* bl1 = (const float*)d_in[6];
    const float* u1  = (const float*)d_in[7];
    const float* bb1 = (const float*)d_in[8];
    const float* fcW = (const float*)d_in[9];
    const float* fcb = (const float*)d_in[10];
    float* out = (float*)d_out;

    __nv_bfloat16 *xhi, *xlo, *h1hi, *h1lo, *h2hi, *h2lo;
    __nv_bfloat16 *w0hi, *w0lo, *w1hi, *w1lo, *fwhi, *fwlo;
    cudaGetSymbolAddress((void**)&xhi,  g_xhi);
    cudaGetSymbolAddress((void**)&xlo,  g_xlo);
    cudaGetSymbolAddress((void**)&h1hi, g_h1hi);
    cudaGetSymbolAddress((void**)&h1lo, g_h1lo);
    cudaGetSymbolAddress((void**)&h2hi, g_h2hi);
    cudaGetSymbolAddress((void**)&h2lo, g_h2lo);
    cudaGetSymbolAddress((void**)&w0hi, g_W0hi);
    cudaGetSymbolAddress((void**)&w0lo, g_W0lo);
    cudaGetSymbolAddress((void**)&w1hi, g_W1hi);
    cudaGetSymbolAddress((void**)&w1lo, g_W1lo);
    cudaGetSymbolAddress((void**)&fwhi, g_fWhi);
    cudaGetSymbolAddress((void**)&fwlo, g_fWlo);

    cudaFuncSetAttribute(layer_tc<DIN>, cudaFuncAttributeMaxDynamicSharedMemorySize, L_SMEM);
    cudaFuncSetAttribute(layer_tc<H_>,  cudaFuncAttributeMaxDynamicSharedMemorySize, L_SMEM);
    cudaFuncSetAttribute(fc_tc,         cudaFuncAttributeMaxDynamicSharedMemorySize, F_SMEM);

    split_kernel<<<1024, 256>>>(x,   xhi,  xlo,  B_ * T_ * DIN);
    split_kernel<<<64,   256>>>(W0,  w0hi, w0lo, H_ * DIN);
    split_kernel<<<256,  256>>>(W1,  w1hi, w1lo, H_ * H_);
    split_kernel<<<64,   256>>>(fcW, fwhi, fwlo, DOUT * H_);

    dim3 lgrid(B_, H_ / 256);         // (64, 2)
    layer_tc<DIN><<<lgrid, TPB, L_SMEM>>>(xhi, xlo, w0hi, w0lo, bl0, u0, bb0, h1hi, h1lo);
    layer_tc<H_> <<<lgrid, TPB, L_SMEM>>>(h1hi, h1lo, w1hi, w1lo, bl1, u1, bb1, h2hi, h2lo);
    dim3 fgrid(B_, 2);                // (64, 2)
    fc_tc<<<fgrid, TPB, F_SMEM>>>(h2hi, h2lo, fwhi, fwlo, fcb, out);
}

// round 14
// speedup vs baseline: 1.0611x; 1.0372x over previous
#include <cuda_runtime.h>
#include <cuda_bf16.h>
#include <cstdint>

#define B_   64
#define T_   2048
#define DIN  128
#define H_   512
#define DOUT 128

#define KC   64      // K elems per chunk (128B bf16 rows)
#define TPB  256

#if defined(__CUDA_ARCH__) && (defined(__CUDA_ARCH_FEAT_SM103_ALL) || defined(__CUDA_ARCH_FEAT_SM100_ALL))
#define USE_TC 1
#else
#define USE_TC 0
#endif

// idesc kind::f16: dtype=F32(1<<4) atype=BF16(1<<7) btype=BF16(1<<10) N=128(16<<17) M=128(8<<24)
#define IDESC_128x128 0x8200490u

// SMEM: [0:4) tmem ptr; mbar at 8; W buf at 1024 (32KB); X bufs (2x32KB)
#define SM_MBAR  8
#define SM_W     1024
#define SM_X0    (1024 + 32768)
#define XBUF_SZ  32768
#define L_SMEM   (1024 + 32768 + 2*32768)   // 99328 -> occ 2 (TMEM 2x256=512 OK)
#define F_SMEM   (1024 + 32768 + 32768)     // 66560 -> occ 3 (TMEM 3x128=384 OK)

// ---------------- scratch: planar bf16 hi/lo ----------------
__device__ __nv_bfloat16 g_xhi[(size_t)B_ * T_ * DIN];
__device__ __nv_bfloat16 g_xlo[(size_t)B_ * T_ * DIN];
__device__ __nv_bfloat16 g_h1hi[(size_t)B_ * T_ * H_];
__device__ __nv_bfloat16 g_h1lo[(size_t)B_ * T_ * H_];
__device__ __nv_bfloat16 g_h2hi[(size_t)B_ * T_ * H_];
__device__ __nv_bfloat16 g_h2lo[(size_t)B_ * T_ * H_];
__device__ __nv_bfloat16 g_W0hi[H_ * DIN];
__device__ __nv_bfloat16 g_W0lo[H_ * DIN];
__device__ __nv_bfloat16 g_W1hi[H_ * H_];
__device__ __nv_bfloat16 g_W1lo[H_ * H_];
__device__ __nv_bfloat16 g_fWhi[DOUT * H_];
__device__ __nv_bfloat16 g_fWlo[DOUT * H_];

#if USE_TC
// ---------------- PTX helpers ----------------
__device__ __forceinline__ uint32_t smem_to_u32(const void* p) {
    uint32_t a;
    asm("{ .reg .u64 t; cvta.to.shared.u64 t, %1; cvt.u32.u64 %0, t; }" : "=r"(a) : "l"(p));
    return a;
}
__device__ __forceinline__ uint32_t elect_one_pred() {
    uint32_t p;
    asm volatile("{\n\t.reg .pred p;\n\telect.sync _|p, 0xFFFFFFFF;\n\tselp.b32 %0, 1, 0, p;\n\t}" : "=r"(p));
    return p;
}
#define MBAR_INIT(a, c) asm volatile("mbarrier.init.shared.b64 [%0], %1;" :: "r"(a), "r"(c) : "memory")
#define MBAR_INVAL(a)   asm volatile("mbarrier.inval.shared.b64 [%0];" :: "r"(a) : "memory")
#define MBAR_WAIT(a, ph) do {                                                       \
    uint32_t _m = (a), _p = (ph), _d;                                               \
    asm volatile("{\n\t.reg .pred p;\n\t"                                           \
        "mbarrier.try_wait.parity.acquire.cta.shared::cta.b64 p, [%1], %2;\n\t"     \
        "selp.b32 %0, 1, 0, p;\n\t}" : "=r"(_d) : "r"(_m), "r"(_p) : "memory");     \
    if (!_d) {                                                                      \
        asm volatile("{\n\t.reg .pred P1;\n\tWL_%=:\n\t"                            \
            "mbarrier.try_wait.parity.acquire.cta.shared::cta.b64 P1, [%0], %1, 0x989680;\n\t" \
            "@P1 bra.uni WD_%=;\n\tbra.uni WL_%=;\n\tWD_%=:\n\t}"                   \
            :: "r"(_m), "r"(_p) : "memory");                                        \
    }                                                                               \
} while (0)
#define TC_ALLOC(sa, n)   asm volatile("tcgen05.alloc.cta_group::1.sync.aligned.shared::cta.b32 [%0], %1;" :: "r"(sa), "r"(n) : "memory")
#define TC_DEALLOC(t, n)  asm volatile("tcgen05.dealloc.cta_group::1.sync.aligned.b32 %0, %1;" :: "r"(t), "r"(n))
#define TC_RELINQ()       asm volatile("tcgen05.relinquish_alloc_permit.cta_group::1.sync.aligned;")
#define TC_COMMIT(mb)     asm volatile("tcgen05.commit.cta_group::1.mbarrier::arrive::one.shared::cluster.b64 [%0];" :: "r"(mb) : "memory")
#define TC_WAIT_LD()      asm volatile("tcgen05.wait::ld.sync.aligned;" ::: "memory")
#define TC_FENCE_BEFORE() asm volatile("tcgen05.fence::before_thread_sync;" ::: "memory")
#define TC_FENCE_AFTER()  asm volatile("tcgen05.fence::after_thread_sync;" ::: "memory")
#define FENCE_ASYNC()     asm volatile("fence.proxy.async.shared::cta;" ::: "memory")
#define CP_ASYNC16(d, s)  asm volatile("cp.async.cg.shared.global [%0], [%1], 16;" :: "r"(d), "l"(s) : "memory")
#define CP_COMMIT()       asm volatile("cp.async.commit_group;" ::: "memory")
#define CP_WAIT0()        asm volatile("cp.async.wait_group 0;" ::: "memory")

__device__ __forceinline__ void mma_f16_ss(uint32_t d, uint64_t ad, uint64_t bd, uint32_t en) {
    asm volatile(
        "{\n\t.reg .pred p;\n\tsetp.ne.u32 p, %4, 0;\n\t"
        "tcgen05.mma.cta_group::1.kind::f16 [%0], %1, %2, %3, {%5, %5, %5, %5}, p;\n\t}"
        :: "r"(d), "l"(ad), "l"(bd), "r"(IDESC_128x128), "r"(en), "r"(0u) : "memory");
}
__device__ __forceinline__ uint64_t mk_desc(uint32_t addr) {
    return ((uint64_t)2 << 61) | ((uint64_t)1 << 46) | ((uint64_t)64 << 32)
         | ((uint64_t)1 << 16) | ((uint64_t)(addr >> 4) & 0x3FFF);
}
#define LDTM_X32(r, a)                                                              \
    asm volatile("tcgen05.ld.sync.aligned.32x32b.x32.b32 "                          \
        "{%0,%1,%2,%3,%4,%5,%6,%7,%8,%9,%10,%11,%12,%13,%14,%15,"                   \
        "%16,%17,%18,%19,%20,%21,%22,%23,%24,%25,%26,%27,%28,%29,%30,%31}, [%32];"  \
        : "=r"((r)[0]),"=r"((r)[1]),"=r"((r)[2]),"=r"((r)[3]),                       \
          "=r"((r)[4]),"=r"((r)[5]),"=r"((r)[6]),"=r"((r)[7]),                       \
          "=r"((r)[8]),"=r"((r)[9]),"=r"((r)[10]),"=r"((r)[11]),                     \
          "=r"((r)[12]),"=r"((r)[13]),"=r"((r)[14]),"=r"((r)[15]),                   \
          "=r"((r)[16]),"=r"((r)[17]),"=r"((r)[18]),"=r"((r)[19]),                   \
          "=r"((r)[20]),"=r"((r)[21]),"=r"((r)[22]),"=r"((r)[23]),                   \
          "=r"((r)[24]),"=r"((r)[25]),"=r"((r)[26]),"=r"((r)[27]),                   \
          "=r"((r)[28]),"=r"((r)[29]),"=r"((r)[30]),"=r"((r)[31]) : "r"(a))

// load one 128-row x 64-bf16 hi/lo pair: 256 threads, plane = tid>>7, row = tid&127.
__device__ __forceinline__ void load_pair(uint32_t dstbase,
        const __nv_bfloat16* __restrict__ hi, const __nv_bfloat16* __restrict__ lo,
        size_t row0, int K, int kc_e, int tid) {
    const int row = tid & 127;
    const char* src = (const char*)((tid < 128 ? hi : lo) + (row0 + row) * (size_t)K + kc_e);
    const uint32_t dst = dstbase + (uint32_t)(tid >> 7) * 16384;
    #pragma unroll
    for (int p = 0; p < 8; p++) {
        uint32_t off = row * 128 + p * 16;
        uint32_t sw = off ^ ((off >> 3) & 0x70);
        CP_ASYNC16(dst + sw, src + p * 16);
    }
}

// 12 MMA dispatches: (Wh,Xh)+(Wh,Xl)+(Wl,Xh) x 4 K16-steps, N=128.
__device__ __forceinline__ void issue12(uint32_t smb, uint32_t xb, uint32_t dacc, int first) {
    const uint64_t dWH = mk_desc(smb + SM_W), dWL = mk_desc(smb + SM_W + 16384);
    const uint64_t dXH = mk_desc(xb), dXL = mk_desc(xb + 16384);
    #pragma unroll
    for (int k = 0; k < 4; k++) {
        const uint64_t o = (uint64_t)(k * 2);
        mma_f16_ss(dacc, dWH + o, dXH + o, (first && k == 0) ? 0u : 1u);
        mma_f16_ss(dacc, dWH + o, dXL + o, 1u);
        mma_f16_ss(dacc, dWL + o, dXH + o, 1u);
    }
}
#endif  // USE_TC

// ---------------- merged fp32 -> planar bf16 hi/lo split ----------------
__global__ void split_all(const float* __restrict__ x,  const float* __restrict__ W0,
                          const float* __restrict__ W1, const float* __restrict__ fcW,
                          __nv_bfloat16* __restrict__ xhi,  __nv_bfloat16* __restrict__ xlo,
                          __nv_bfloat16* __restrict__ w0hi, __nv_bfloat16* __restrict__ w0lo,
                          __nv_bfloat16* __restrict__ w1hi, __nv_bfloat16* __restrict__ w1lo,
                          __nv_bfloat16* __restrict__ fwhi, __nv_bfloat16* __restrict__ fwlo) {
    const int NX = B_ * T_ * DIN, NW0 = H_ * DIN, NW1 = H_ * H_, NF = DOUT * H_;
    const int total = NX + NW0 + NW1 + NF;
    for (int i = blockIdx.x * blockDim.x + threadIdx.x; i < total; i += gridDim.x * blockDim.x) {
        const float* s; __nv_bfloat16 *ph, *pl; int j;
        if (i < NX)                  { s = x;   ph = xhi;  pl = xlo;  j = i; }
        else if (i < NX + NW0)       { s = W0;  ph = w0hi; pl = w0lo; j = i - NX; }
        else if (i < NX + NW0 + NW1) { s = W1;  ph = w1hi; pl = w1lo; j = i - NX - NW0; }
        else                         { s = fcW; ph = fwhi; pl = fwlo; j = i - NX - NW0 - NW1; }
        float v = s[j];
        __nv_bfloat16 h = __float2bfloat16(v);
        ph[j] = h;
        pl[j] = __float2bfloat16(v - __bfloat162float(h));
    }
}

// ================ fused layer: kc-outer tilegroups (TG=2) + in-register scan ================
// grid (H_/128, B_), block 256, occ 2. TMEM 256 cols (2 tile accumulators).
// Race-free protocol: wait commit[s-1] BEFORE issuing commit[s] (no parity aliasing).
template <int K>
__global__ void __launch_bounds__(TPB)
layer_tc(const __nv_bfloat16* __restrict__ Xhi, const __nv_bfloat16* __restrict__ Xlo,
         const __nv_bfloat16* __restrict__ Whi, const __nv_bfloat16* __restrict__ Wlo,
         const float* __restrict__ bl, const float* __restrict__ u, const float* __restrict__ bb,
         __nv_bfloat16* __restrict__ Hhi, __nv_bfloat16* __restrict__ Hlo) {
    extern __shared__ char smem[];
    const int tid = threadIdx.x;
    const int h0 = blockIdx.x * 128;
    const int batch = blockIdx.y;
#if USE_TC
    constexpr int C = K / KC;            // K chunks
    constexpr int TG = 2;                // tiles per group
    constexpr int NTG = T_ / (128 * TG); // 8
    constexpr int STEPS = C * TG;
    const uint32_t smb = smem_to_u32(smem);
    const int wid = tid >> 5;

    if (tid == 0) MBAR_INIT(smb + SM_MBAR, 1);
    if (wid == 0) { TC_ALLOC(smb, 256); TC_RELINQ(); }
    __syncthreads();
    uint32_t tmem;
    asm volatile("ld.shared.b32 %0, [%1];" : "=r"(tmem) : "r"(smb));

    float carry = 0.0f, uu = 0.0f, bi = 0.0f;
    if (tid < 128) { uu = u[h0 + tid]; bi = bl[h0 + tid] + bb[h0 + tid]; }

    int gstep = 0;   // global step index == commits issued before current step

    // preload step 0 of tg 0: W[kc0] + X[tile0, kc0] -> xbuf0
    load_pair(smb + SM_W,  Whi, Wlo, (size_t)h0, K, 0, tid);
    load_pair(smb + SM_X0, Xhi, Xlo, (size_t)batch * T_, K, 0, tid);
    CP_COMMIT();

    for (int tg = 0; tg < NTG; tg++) {
        for (int s = 0; s < STEPS; s++) {
            const int kc = s >> 1, tt = s & 1;
            CP_WAIT0();                                     // this step's tiles loaded
            if (gstep >= 1)                                 // prev step's MMAs done
                MBAR_WAIT(smb + SM_MBAR, (gstep - 1) & 1);  //   (completion #gstep)
            __syncthreads();
            FENCE_ASYNC();
            if (wid == 0 && elect_one_pred()) {
                issue12(smb, smb + SM_X0 + (uint32_t)tt * XBUF_SZ, tmem + tt * 128, kc == 0);
                TC_COMMIT(smb + SM_MBAR);
            }
            const int next = s + 1;
            if (next < STEPS) {
                const int nkc = next >> 1, ntt = next & 1;
                if (ntt == 0) {
                    // W overwrite: needs THIS step's MMAs done (completion #gstep+1;
                    // commit #gstep+2 can't be issued until all threads pass next sync)
                    MBAR_WAIT(smb + SM_MBAR, gstep & 1);
                    load_pair(smb + SM_W, Whi, Wlo, (size_t)h0, K, nkc * KC, tid);
                }
                // X overwrite: buffer last read by MMA[s-1], waited at top of this step
                load_pair(smb + SM_X0 + (uint32_t)ntt * XBUF_SZ, Xhi, Xlo,
                          (size_t)batch * T_ + (tg * TG + ntt) * 128, K, nkc * KC, tid);
                CP_COMMIT();
            }
            gstep++;
        }
        MBAR_WAIT(smb + SM_MBAR, (gstep - 1) & 1);  // last commit of this tilegroup
        if (tg + 1 < NTG) {                         // preload next tg (overlaps scan)
            load_pair(smb + SM_W,  Whi, Wlo, (size_t)h0, K, 0, tid);
            load_pair(smb + SM_X0, Xhi, Xlo,
                      (size_t)batch * T_ + (tg + 1) * TG * 128, K, 0, tid);
            CP_COMMIT();
        }
        if (tid < 128) {
            TC_FENCE_AFTER();
            #pragma unroll
            for (int tt = 0; tt < TG; tt++) {
                #pragma unroll
                for (int cb = 0; cb < 4; cb++) {
                    uint32_t d[32];
                    LDTM_X32(d, tmem + tt * 128 + cb * 32);
                    TC_WAIT_LD();
                    const int tglob = (tg * TG + tt) * 128 + cb * 32;
                    const size_t base = ((size_t)batch * T_ + tglob) * H_ + h0 + tid;
                    #pragma unroll
                    for (int i = 0; i < 32; i++) {
                        float p = __uint_as_float(d[i]) + bi;
                        carry = fmaxf(fmaf(uu, carry, p), 0.0f);
                        __nv_bfloat16 hb = __float2bfloat16(carry);
                        Hhi[base + (size_t)i * H_] = hb;
                        Hlo[base + (size_t)i * H_] = __float2bfloat16(carry - __bfloat162float(hb));
                    }
                }
            }
            TC_FENCE_BEFORE();
        }
        __syncthreads();   // scan done before next tg's en=0 MMA overwrites TMEM
    }
    if (tid == 0) MBAR_INVAL(smb + SM_MBAR);
    __syncthreads();
    if (wid == 0) TC_DEALLOC(tmem, 256);
#else
    // SIMT fallback: thread tid<128 owns channel h0+tid
    float* xrow = (float*)smem;
    const int hh = h0 + (tid < 128 ? tid : 0);
    const float uu = u[hh], bi = bl[hh] + bb[hh];
    const __nv_bfloat16* wh = Whi + (size_t)hh * K;
    const __nv_bfloat16* wl = Wlo + (size_t)hh * K;
    float hcar = 0.0f;
    for (int t = 0; t < T_; t++) {
        __syncthreads();
        size_t xr = ((size_t)batch * T_ + t) * K;
        for (int i = tid; i < K; i += blockDim.x)
            xrow[i] = __bfloat162float(Xhi[xr + i]) + __bfloat162float(Xlo[xr + i]);
        __syncthreads();
        if (tid < 128) {
            float acc = 0.0f;
            for (int k = 0; k < K; k++)
                acc += (__bfloat162float(wh[k]) + __bfloat162float(wl[k])) * xrow[k];
            hcar = fmaxf(acc + bi + uu * hcar, 0.0f);
            size_t oi = ((size_t)batch * T_ + t) * H_ + hh;
            __nv_bfloat16 hb = __float2bfloat16(hcar);
            Hhi[oi] = hb;
            Hlo[oi] = __float2bfloat16(hcar - __bfloat162float(hb));
        }
    }
#endif
}

// ================ FC: out[b,t,o] = h2 . fcW[o,:] + fcb[o] ================
// grid (T_/128, B_), block 256, occ 3. 1 tile per CTA, K=512 in 8 serial chunks.
__global__ void __launch_bounds__(TPB)
fc_tc(const __nv_bfloat16* __restrict__ Xhi, const __nv_bfloat16* __restrict__ Xlo,
      const __nv_bfloat16* __restrict__ Whi, const __nv_bfloat16* __restrict__ Wlo,
      const float* __restrict__ bias, float* __restrict__ out) {
    extern __shared__ char smem[];
    const int tid = threadIdx.x;
    const int t0 = blockIdx.x * 128;
    const int batch = blockIdx.y;
#if USE_TC
    constexpr int C = H_ / KC;   // 8
    const uint32_t smb = smem_to_u32(smem);
    const int wid = tid >> 5;

    if (tid == 0) MBAR_INIT(smb + SM_MBAR, 1);
    if (wid == 0) { TC_ALLOC(smb, 128); TC_RELINQ(); }
    __syncthreads();
    uint32_t tmem;
    asm volatile("ld.shared.b32 %0, [%1];" : "=r"(tmem) : "r"(smb));

    for (int c = 0; c < C; c++) {
        if (c) MBAR_WAIT(smb + SM_MBAR, (c - 1) & 1);  // prev MMAs done -> smem reusable
        load_pair(smb + SM_W,  Whi, Wlo, (size_t)0, H_, c * KC, tid);
        load_pair(smb + SM_X0, Xhi, Xlo, (size_t)batch * T_ + t0, H_, c * KC, tid);
        CP_COMMIT();
        CP_WAIT0();
        __syncthreads();
        FENCE_ASYNC();
        if (wid == 0 && elect_one_pred()) {
            issue12(smb, smb + SM_X0, tmem, c == 0);
            TC_COMMIT(smb + SM_MBAR);
        }
    }
    MBAR_WAIT(smb + SM_MBAR, (C - 1) & 1);
    if (tid < 128) {
        TC_FENCE_AFTER();
        const float bo = bias[tid];
        #pragma unroll
        for (int cb = 0; cb < 4; cb++) {
            uint32_t d[32];
            LDTM_X32(d, tmem + cb * 32);
            TC_WAIT_LD();
            float* op = out + ((size_t)batch * T_ + t0 + cb * 32) * DOUT + tid;
            #pragma unroll
            for (int i = 0; i < 32; i++)
                op[(size_t)i * DOUT] = __uint_as_float(d[i]) + bo;
        }
        TC_FENCE_BEFORE();
    }
    __syncthreads();
    if (tid == 0) MBAR_INVAL(smb + SM_MBAR);
    __syncthreads();
    if (wid == 0) TC_DEALLOC(tmem, 128);
#else
    // SIMT fallback
    float* xrow = (float*)smem;
    const __nv_bfloat16* wh = Whi + (size_t)(tid < 128 ? tid : 0) * H_;
    const __nv_bfloat16* wl = Wlo + (size_t)(tid < 128 ? tid : 0) * H_;
    float bo = (tid < 128) ? bias[tid] : 0.0f;
    for (int tt = 0; tt < 128; tt++) {
        const int t = t0 + tt;
        __syncthreads();
        size_t xr = ((size_t)batch * T_ + t) * H_;
        for (int i = tid; i < H_; i += blockDim.x)
            xrow[i] = __bfloat162float(Xhi[xr + i]) + __bfloat162float(Xlo[xr + i]);
        __syncthreads();
        if (tid < 128) {
            float acc = 0.0f;
            for (int k = 0; k < H_; k++)
                acc += (__bfloat162float(wh[k]) + __bfloat162float(wl[k])) * xrow[k];
            out[((size_t)batch * T_ + t) * DOUT + tid] = acc + bo;
        }
    }
#endif
}

extern "C" void kernel_launch(void* const* d_in, const int* in_sizes, int n_in,
                              void* d_out, int out_size) {
    const float* x   = (const float*)d_in[0];
    const float* W0  = (const float*)d_in[1];
    const float* bl0 = (const float*)d_in[2];
    const float* u0  = (const float*)d_in[3];
    const float* bb0 = (const float*)d_in[4];
    const float* W1  = (const float*)d_in[5];
    const float* bl1 = (const float*)d_in[6];
    const float* u1  = (const float*)d_in[7];
    const float* bb1 = (const float*)d_in[8];
    const float* fcW = (const float*)d_in[9];
    const float* fcb = (const float*)d_in[10];
    float* out = (float*)d_out;

    __nv_bfloat16 *xhi, *xlo, *h1hi, *h1lo, *h2hi, *h2lo;
    __nv_bfloat16 *w0hi, *w0lo, *w1hi, *w1lo, *fwhi, *fwlo;
    cudaGetSymbolAddress((void**)&xhi,  g_xhi);
    cudaGetSymbolAddress((void**)&xlo,  g_xlo);
    cudaGetSymbolAddress((void**)&h1hi, g_h1hi);
    cudaGetSymbolAddress((void**)&h1lo, g_h1lo);
    cudaGetSymbolAddress((void**)&h2hi, g_h2hi);
    cudaGetSymbolAddress((void**)&h2lo, g_h2lo);
    cudaGetSymbolAddress((void**)&w0hi, g_W0hi);
    cudaGetSymbolAddress((void**)&w0lo, g_W0lo);
    cudaGetSymbolAddress((void**)&w1hi, g_W1hi);
    cudaGetSymbolAddress((void**)&w1lo, g_W1lo);
    cudaGetSymbolAddress((void**)&fwhi, g_fWhi);
    cudaGetSymbolAddress((void**)&fwlo, g_fWlo);

    cudaFuncSetAttribute(layer_tc<DIN>, cudaFuncAttributeMaxDynamicSharedMemorySize, L_SMEM);
    cudaFuncSetAttribute(layer_tc<H_>,  cudaFuncAttributeMaxDynamicSharedMemorySize, L_SMEM);
    cudaFuncSetAttribute(fc_tc,         cudaFuncAttributeMaxDynamicSharedMemorySize, F_SMEM);

    split_all<<<2048, 256>>>(x, W0, W1, fcW, xhi, xlo, w0hi, w0lo, w1hi, w1lo, fwhi, fwlo);

    dim3 lgrid(H_ / 128, B_);         // (4, 64)
    layer_tc<DIN><<<lgrid, TPB, L_SMEM>>>(xhi, xlo, w0hi, w0lo, bl0, u0, bb0, h1hi, h1lo);
    layer_tc<H_> <<<lgrid, TPB, L_SMEM>>>(h1hi, h1lo, w1hi, w1lo, bl1, u1, bb1, h2hi, h2lo);
    dim3 fgrid(T_ / 128, B_);         // (16, 64)
    fc_tc<<<fgrid, TPB, F_SMEM>>>(h2hi, h2lo, fwhi, fwlo, fcb, out);
}